// round 4
// baseline (speedup 1.0000x reference)
#include <cuda_runtime.h>

// x (2,128,7,7) fp32 -> causality maps (2,128,128) fp32.
// p=1 => Lehmer cross-sums are rank-1 separable:
//   sum_ij cross = S[m]*S[n], sum_ij cross^2 = Q[m]*Q[n].
// Latency-bound: 64 blocks x 1024 threads, each block redundantly computes the
// tiny reduction (input is L2-resident) and writes one 512-element output slab.

#define EPS 1e-8f
#define C_CH 128
#define F_SP 49
#define CF (C_CH * F_SP)
#define SLABS 32               // output slabs per batch (512 outputs each)

__global__ __launch_bounds__(1024, 1)
void causality_kernel(const float* __restrict__ x, float* __restrict__ out) {
    const int b    = blockIdx.x >> 5;
    const int slab = blockIdx.x & (SLABS - 1);
    const int tid  = threadIdx.x;
    const int ch   = tid >> 3;              // channel 0..127 (8 lanes each)
    const int l8   = tid & 7;
    const int lid  = tid & 31;
    const int wid  = tid >> 5;              // 32 warps

    __shared__ float S[C_CH];
    __shared__ float Q[C_CH];
    __shared__ float invLd[C_CH];
    __shared__ float red[32];

    const float* __restrict__ xc = x + b * CF + ch * F_SP + l8;

    // ---- fused load: 6 unconditional LDGs (j = l8 + 8i <= 47) + 1 predicated ----
    float v0 = __ldg(xc);
    float v1 = __ldg(xc + 8);
    float v2 = __ldg(xc + 16);
    float v3 = __ldg(xc + 24);
    float v4 = __ldg(xc + 32);
    float v5 = __ldg(xc + 40);

    float s = ((v0 + v1) + (v2 + v3)) + (v4 + v5);
    float q = fmaf(v0, v0, fmaf(v1, v1, fmaf(v2, v2,
              fmaf(v3, v3, fmaf(v4, v4, v5 * v5)))));
    float m = fmaxf(fmaxf(fmaxf(v0, v1), fmaxf(v2, v3)), fmaxf(v4, v5));

    if (l8 == 0) {                           // j = 48, last spatial element
        float v6 = __ldg(xc + 48);
        s += v6;
        q = fmaf(v6, v6, q);
        m = fmaxf(m, v6);
    }

    // ---- 8-lane reduce for s,q; full-warp reduce for max ----
    #pragma unroll
    for (int o = 1; o < 8; o <<= 1) {
        s += __shfl_xor_sync(0xffffffffu, s, o);
        q += __shfl_xor_sync(0xffffffffu, q, o);
        m = fmaxf(m, __shfl_xor_sync(0xffffffffu, m, o));
    }
    #pragma unroll
    for (int o = 8; o < 32; o <<= 1)
        m = fmaxf(m, __shfl_xor_sync(0xffffffffu, m, o));

    if (lid == 0) red[wid] = m;
    __syncthreads();

    // every warp redundantly folds the 32 warp maxima (no extra barrier)
    float v = red[lid];
    #pragma unroll
    for (int o = 1; o < 32; o <<= 1)
        v = fmaxf(v, __shfl_xor_sync(0xffffffffu, v, o));
    const float inv = __fdividef(1.0f, v + EPS);

    if (l8 == 0) {
        float sn = s * inv;
        float qn = q * inv * inv;
        S[ch] = sn;
        Q[ch] = qn;
        // Ld = (Q + 2 eps S + F eps^2 + eps)/(S + F eps + eps) + eps
        float nd = qn + 2.0f * EPS * sn + (float)F_SP * EPS * EPS + EPS;
        float dd = sn + (float)F_SP * EPS + EPS;
        invLd[ch] = __fdividef(dd, nd + EPS * dd);   // = 1/(nd/dd + eps)
    }
    __syncthreads();

    // ---- combine: this block's 512-element slab, threads 0..511 ----
    if (tid < 512) {
        const float ff_e2 = (float)(F_SP * F_SP) * EPS * EPS;
        const float ff_e  = (float)(F_SP * F_SP) * EPS;
        int idx = slab * 512 + tid;
        int mm = idx >> 7;
        int nn = idx & 127;
        float ss  = S[mm] * S[nn];
        float num = fmaf(Q[mm], Q[nn], fmaf(2.0f * EPS, ss, ff_e2 + EPS));
        float den = ss + (ff_e + EPS);
        float r   = __fdividef(num, den) + EPS;
        out[b * (C_CH * C_CH) + idx] = r * invLd[nn];
    }
}

extern "C" void kernel_launch(void* const* d_in, const int* in_sizes, int n_in,
                              void* d_out, int out_size) {
    const float* x = (const float*)d_in[0];
    float* out = (float*)d_out;
    int B = in_sizes[0] / CF;   // = 2
    causality_kernel<<<B * SLABS, 1024>>>(x, out);
}

// round 5
// speedup vs baseline: 1.0337x; 1.0337x over previous
#include <cuda_runtime.h>

// x (2,128,7,7) fp32 -> causality maps (2,128,128) fp32.
// p=1 => Lehmer cross-sums are rank-1 separable:
//   sum_ij cross = S[m]*S[n], sum_ij cross^2 = Q[m]*Q[n].
// 64 blocks x 512 threads; each block redundantly computes the tiny reduction
// (input L2-resident after first touch) and writes one 512-element slab.
// Single-barrier design: RAW S/Q stored pre-barrier (normalization commutes),
// inv and invLd applied on the fly in the combine.

#define EPS 1e-8f
#define C_CH 128
#define F_SP 49
#define CF (C_CH * F_SP)
#define SLABS 32

__global__ __launch_bounds__(512, 1)
void causality_kernel(const float* __restrict__ x, float* __restrict__ out) {
    const int b    = blockIdx.x >> 5;
    const int slab = blockIdx.x & (SLABS - 1);
    const int tid  = threadIdx.x;
    const int ch   = tid >> 2;              // channel 0..127 (4 lanes each)
    const int l4   = tid & 3;
    const int lid  = tid & 31;
    const int wid  = tid >> 5;              // 16 warps

    __shared__ float Sr[C_CH];              // RAW per-channel sum
    __shared__ float Qr[C_CH];              // RAW per-channel sum of squares
    __shared__ float red[16];               // per-warp max

    const float* __restrict__ xc = x + b * CF + ch * F_SP + l4;

    // ---- fully unrolled load: j = l4 + 4*i, i=0..11 (j<=47) + predicated j=48 ----
    float v0  = __ldg(xc);
    float v1  = __ldg(xc + 4);
    float v2  = __ldg(xc + 8);
    float v3  = __ldg(xc + 12);
    float v4  = __ldg(xc + 16);
    float v5  = __ldg(xc + 20);
    float v6  = __ldg(xc + 24);
    float v7  = __ldg(xc + 28);
    float v8  = __ldg(xc + 32);
    float v9  = __ldg(xc + 36);
    float v10 = __ldg(xc + 40);
    float v11 = __ldg(xc + 44);

    float s = (((v0 + v1) + (v2 + v3)) + ((v4 + v5) + (v6 + v7)))
            + (((v8 + v9) + (v10 + v11)));
    float q = fmaf(v0, v0, fmaf(v1, v1, fmaf(v2, v2, fmaf(v3, v3,
              fmaf(v4, v4, fmaf(v5, v5, fmaf(v6, v6, fmaf(v7, v7,
              fmaf(v8, v8, fmaf(v9, v9, fmaf(v10, v10, v11 * v11)))))))))));
    float m = fmaxf(fmaxf(fmaxf(v0, v1), fmaxf(v2, v3)),
              fmaxf(fmaxf(fmaxf(v4, v5), fmaxf(v6, v7)),
                    fmaxf(fmaxf(v8, v9), fmaxf(v10, v11))));

    if (l4 == 0) {                          // j = 48
        float v12 = __ldg(xc + 48);
        s += v12;
        q = fmaf(v12, v12, q);
        m = fmaxf(m, v12);
    }

    // ---- 4-lane reduce s,q ; full-warp reduce max ----
    #pragma unroll
    for (int o = 1; o < 4; o <<= 1) {
        s += __shfl_xor_sync(0xffffffffu, s, o);
        q += __shfl_xor_sync(0xffffffffu, q, o);
        m = fmaxf(m, __shfl_xor_sync(0xffffffffu, m, o));
    }
    #pragma unroll
    for (int o = 4; o < 32; o <<= 1)
        m = fmaxf(m, __shfl_xor_sync(0xffffffffu, m, o));

    // RAW stats to SMEM (independent of max) + warp max — then ONE barrier
    if (l4 == 0) { Sr[ch] = s; Qr[ch] = q; }
    if (lid == 0) red[wid] = m;
    __syncthreads();

    // every warp redundantly folds the 16 warp maxima (no second barrier)
    float v = red[lid & 15];
    #pragma unroll
    for (int o = 1; o < 16; o <<= 1)
        v = fmaxf(v, __shfl_xor_sync(0xffffffffu, v, o));
    const float inv  = __fdividef(1.0f, v + EPS);
    const float inv2 = inv * inv;

    // ---- combine: one output per thread ----
    const float ff_e2 = (float)(F_SP * F_SP) * EPS * EPS;
    const float ff_e  = (float)(F_SP * F_SP) * EPS;
    int idx = slab * 512 + tid;
    int mm = idx >> 7;
    int nn = idx & 127;

    float sm = Sr[mm] * inv;
    float sn = Sr[nn] * inv;
    float qm = Qr[mm] * inv2;
    float qn = Qr[nn] * inv2;

    // Lehmer numerator matrix term
    float ss  = sm * sn;
    float num = fmaf(qm, qn, fmaf(2.0f * EPS, ss, ff_e2 + EPS));
    float den = ss + (ff_e + EPS);
    float r   = __fdividef(num, den) + EPS;

    // per-column Lehmer denominator, on the fly:
    // Ld = (qn + 2 eps sn + F eps^2 + eps)/(sn + F eps + eps) + eps
    float nd = qn + 2.0f * EPS * sn + (float)F_SP * EPS * EPS + EPS;
    float dd = sn + (float)F_SP * EPS + EPS;
    float iLd = __fdividef(dd, fmaf(EPS, dd, nd));   // = 1/(nd/dd + eps)

    out[b * (C_CH * C_CH) + idx] = r * iLd;
}

extern "C" void kernel_launch(void* const* d_in, const int* in_sizes, int n_in,
                              void* d_out, int out_size) {
    const float* x = (const float*)d_in[0];
    float* out = (float*)d_out;
    int B = in_sizes[0] / CF;   // = 2
    causality_kernel<<<B * SLABS, 512>>>(x, out);
}